// round 10
// baseline (speedup 1.0000x reference)
#include <cuda_runtime.h>
#include <math.h>

#define N_BOXES 256
#define N_VIEWS 6
#define P_TOT   (N_BOXES * N_VIEWS)   // 1536
#define C_FEAT  256
#define HF      116
#define WF      200
#define HW      (HF * WF)             // 23200
#define EPS     1e-8f

#define NBLK    148                   // one block per SM
#define NTHR    384                   // 12 warps: 0..10 pairs, 11 = scout
#define NWARP   12
#define NCHUNK  (P_TOT / 32)          // 48
#define FSCALE  4294967296.0          // 2^32 fixed-point scale

// Deterministic cross-block accumulators (integer atomics only)
__device__ unsigned long long g_sum  = 0ULL;
__device__ int                g_cnt  = 0;
__device__ int                g_done = 0;

// Project pair p; returns valid (0/1), writes packed clamped coords u0c | v0c<<8.
__device__ __forceinline__ int project_pair(int p,
                                            const float* __restrict__ boxes,
                                            const float* __restrict__ Kmat,
                                            const float* __restrict__ Tmat,
                                            const int*   __restrict__ img_sizes,
                                            int* coord_out)
{
    const int n = p / N_VIEWS;
    const int v = p - n * N_VIEWS;
    const float cx = boxes[n * 7 + 0];
    const float cy = boxes[n * 7 + 1];
    const float cz = boxes[n * 7 + 2];

    const float* Tv = Tmat + v * 16;   // 4x4 row-major
    const float pc0 = Tv[0] * cx + Tv[1] * cy + Tv[2]  * cz + Tv[3];
    const float pc1 = Tv[4] * cx + Tv[5] * cy + Tv[6]  * cz + Tv[7];
    const float pc2 = Tv[8] * cx + Tv[9] * cy + Tv[10] * cz + Tv[11];

    const float* Kv = Kmat + v * 9;    // 3x3 row-major
    const float q0 = Kv[0] * pc0 + Kv[1] * pc1 + Kv[2] * pc2;
    const float q1 = Kv[3] * pc0 + Kv[4] * pc1 + Kv[5] * pc2;
    const float q2 = Kv[6] * pc0 + Kv[7] * pc1 + Kv[8] * pc2;

    const float z  = pc2;
    const float u  = q0 / q2;          // ref: u = p2d.x / p2d.z
    const float vv = q1 / z;           // ref: v = p2d.y / p_cam.z

    const float Himg = (float)img_sizes[v * 2 + 0];
    const float Wimg = (float)img_sizes[v * 2 + 1];
    const int u0 = (int)floorf(u  * (float)WF / Wimg);
    const int v0 = (int)floorf(vv * (float)HF / Himg);

    const bool valid = (z > 0.0f) && (u >= 0.0f) && (u < Wimg) &&
                       (vv >= 0.0f) && (vv < Himg) &&
                       (u0 < WF - 1) && (v0 < HF - 1);

    const int u0c = min(max(u0, 0), WF - 2);
    const int v0c = min(max(v0, 0), HF - 2);
    *coord_out = u0c | (v0c << 8);
    return valid ? 1 : 0;
}

__global__ void __launch_bounds__(NTHR, 1)
fused_kernel(const float* __restrict__ boxes,
             const float* __restrict__ feats,
             const float* __restrict__ Kmat,
             const float* __restrict__ Tmat,
             const int*   __restrict__ img_sizes,
             float*       __restrict__ out)
{
    __shared__ int   s_first;
    __shared__ float s_sinv;
    __shared__ float s_stored[C_FEAT];
    __shared__ float s_loss[NWARP];
    __shared__ int   s_lval[NWARP];

    const int tid  = threadIdx.x;
    const int warp = tid >> 5;
    const int lane = tid & 31;

    if (warp == 11) {
        // ================= Scout warp =================
        // 1) Find first = min(p | valid) by chunk-scan with ballot.
        //    If any pair in chunk c is valid, the global minimum is in chunk c.
        int first = 0, fcoord = 0, coord_p0 = 0;
        for (int c = 0; c < NCHUNK; c++) {
            int coord;
            const int valid = project_pair(c * 32 + lane, boxes, Kmat, Tmat,
                                           img_sizes, &coord);
            if (c == 0) coord_p0 = __shfl_sync(0xffffffffu, coord, 0);
            const unsigned m = __ballot_sync(0xffffffffu, valid);
            if (m) {
                const int lead = __ffs(m) - 1;
                first  = c * 32 + lead;
                fcoord = __shfl_sync(0xffffffffu, coord, lead);
                break;
            }
            if (c == NCHUNK - 1) { first = 0; fcoord = coord_p0; } // none valid
        }

        // 2) Gather 'stored' (256 ch x 4 px) with the pair-lane line-sharing
        //    trick: lanes 2j,2j+1 take u0/u0+1 of channel set {chof+16i}.
        const int u0f   = fcoord & 0xFF;
        const int v0f   = (fcoord >> 8) & 0xFF;
        const int viewf = first % N_VIEWS;
        const int du    = lane & 1;
        const int chof  = lane >> 1;
        const float* base = feats + (size_t)viewf * C_FEAT * HW
                                  + (size_t)v0f * WF + u0f + du;
        float y0[16], y1[16];
        #pragma unroll
        for (int i = 0; i < 16; i++) {
            const float* pch = base + (size_t)(chof + i * 16) * HW;
            y0[i] = pch[0];
            y1[i] = pch[WF];
        }
        float sq = 0.0f;
        #pragma unroll
        for (int i = 0; i < 16; i++) {
            const float s2 = y0[i] + y1[i];
            const float sp = __shfl_xor_sync(0xffffffffu, s2, 1);
            const float fm = 0.25f * (s2 + sp);
            if (du == 0) s_stored[chof + i * 16] = fm;
            sq += fm * fm;                 // counted by both du-lanes
        }
        #pragma unroll
        for (int o = 16; o > 0; o >>= 1)
            sq += __shfl_xor_sync(0xffffffffu, sq, o);
        if (lane == 0) {
            s_first = first;
            s_sinv  = 1.0f / fmaxf(sqrtf(0.5f * sq), EPS);
            s_loss[11] = 0.0f;
            s_lval[11] = 0;
        }
    } else {
        // ================= Pair warps (0..10) =================
        const int p_own = blockIdx.x + NBLK * warp;
        float y0[16], y1[16];
        int own_coord = 0, own_valid = 0;
        if (p_own < P_TOT)
            own_valid = project_pair(p_own, boxes, Kmat, Tmat, img_sizes,
                                     &own_coord);
        if (own_valid) {
            const int u0   = own_coord & 0xFF;
            const int v0   = (own_coord >> 8) & 0xFF;
            const int view = p_own % N_VIEWS;
            const int du   = lane & 1;
            const int chof = lane >> 1;
            const float* base = feats + (size_t)view * C_FEAT * HW
                                      + (size_t)v0 * WF + u0 + du;
            #pragma unroll
            for (int i = 0; i < 16; i++) {
                const float* pch = base + (size_t)(chof + i * 16) * HW;
                y0[i] = pch[0];
                y1[i] = pch[WF];
            }
        } else {
            #pragma unroll
            for (int i = 0; i < 16; i++) { y0[i] = 0.0f; y1[i] = 0.0f; }
        }
        // Pre-reduce own sums + self-norm BEFORE the barrier (no stored needed).
        float fm[16];
        float nrm = 0.0f;
        #pragma unroll
        for (int i = 0; i < 16; i++) {
            const float s2 = y0[i] + y1[i];
            const float sp = __shfl_xor_sync(0xffffffffu, s2, 1);
            fm[i] = 0.25f * (s2 + sp);
            nrm += fm[i] * fm[i];
        }

        __syncthreads();   // meet scout: s_stored, s_sinv, s_first ready

        float loss = 0.0f;
        int   cnt  = 0;
        if (own_valid && p_own != s_first) {
            const int chof = lane >> 1;
            float dot = 0.0f;
            #pragma unroll
            for (int i = 0; i < 16; i++)
                dot += fm[i] * s_stored[chof + i * 16];
            #pragma unroll
            for (int o = 16; o > 0; o >>= 1) {
                dot += __shfl_xor_sync(0xffffffffu, dot, o);
                nrm += __shfl_xor_sync(0xffffffffu, nrm, o);
            }
            dot *= 0.5f;   // both du-lanes counted each channel
            nrm *= 0.5f;
            const float inv_i = 1.0f / fmaxf(sqrtf(nrm), EPS);
            loss = 1.0f - dot * inv_i * s_sinv;
            cnt  = 1;
        }
        if (lane == 0) { s_loss[warp] = loss; s_lval[warp] = cnt; }
    }

    // Scout falls through to here; pair warps synced above. One more barrier
    // so all s_loss/s_lval writes are visible. (Scout's barrier pairs with the
    // pair warps' barrier above — every thread executes exactly 2 barriers.)
    if (warp == 11) __syncthreads();
    __syncthreads();

    // ---- Deterministic block sum -> fixed-point global atomics ----
    if (tid == 0) {
        float bsum = 0.0f;
        int   bcnt = 0;
        #pragma unroll
        for (int k = 0; k < NWARP; k++) { bsum += s_loss[k]; bcnt += s_lval[k]; }
        const long long q = llrint((double)bsum * FSCALE);
        atomicAdd(&g_sum, (unsigned long long)q);
        atomicAdd(&g_cnt, bcnt);
        __threadfence();
        const int done = atomicAdd(&g_done, 1);
        if (done == NBLK - 1) {
            const long long tot = (long long)atomicAdd(&g_sum, 0ULL);
            const int n = atomicAdd(&g_cnt, 0);
            out[0] = (n > 0) ? (float)(((double)tot / FSCALE) / (double)n) : 0.0f;
            // reset for next replay (kernel boundary orders this vs next launch)
            g_sum = 0ULL; g_cnt = 0; g_done = 0;
        }
    }
}

extern "C" void kernel_launch(void* const* d_in, const int* in_sizes, int n_in,
                              void* d_out, int out_size)
{
    const float* boxes     = (const float*)d_in[0];  // (256, 7)
    const float* feats     = (const float*)d_in[1];  // (6, 256, 116, 200)
    const float* Kmat      = (const float*)d_in[2];  // (6, 3, 3)
    const float* Tmat      = (const float*)d_in[3];  // (6, 4, 4)
    const int*   img_sizes = (const int*)d_in[4];    // (6, 2)
    float* out = (float*)d_out;

    fused_kernel<<<NBLK, NTHR>>>(boxes, feats, Kmat, Tmat, img_sizes, out);
}

// round 11
// speedup vs baseline: 1.0462x; 1.0462x over previous
#include <cuda_runtime.h>
#include <math.h>

#define N_BOXES 256
#define N_VIEWS 6
#define P_TOT   (N_BOXES * N_VIEWS)   // 1536
#define C_FEAT  256
#define HF      116
#define WF      200
#define HW      (HF * WF)             // 23200
#define EPS     1e-8f

#define NBLK    148                   // one block per SM
#define NTHR    768                   // 24 warps: 0..21 pair-halves, 22 scout
#define NPAIRW  11                    // pairs per block (2 warps each)
#define NCHUNK  (P_TOT / 32)          // 48
#define FSCALE  4294967296.0          // 2^32 fixed-point scale

// Deterministic cross-block accumulators (integer atomics only)
__device__ unsigned long long g_sum  = 0ULL;
__device__ int                g_cnt  = 0;
__device__ int                g_done = 0;

// Project pair p; returns valid (0/1), writes packed clamped coords u0c | v0c<<8.
__device__ __forceinline__ int project_pair(int p,
                                            const float* __restrict__ boxes,
                                            const float* __restrict__ Kmat,
                                            const float* __restrict__ Tmat,
                                            const int*   __restrict__ img_sizes,
                                            int* coord_out)
{
    const int n = p / N_VIEWS;
    const int v = p - n * N_VIEWS;
    const float cx = boxes[n * 7 + 0];
    const float cy = boxes[n * 7 + 1];
    const float cz = boxes[n * 7 + 2];

    const float* Tv = Tmat + v * 16;   // 4x4 row-major
    const float pc0 = Tv[0] * cx + Tv[1] * cy + Tv[2]  * cz + Tv[3];
    const float pc1 = Tv[4] * cx + Tv[5] * cy + Tv[6]  * cz + Tv[7];
    const float pc2 = Tv[8] * cx + Tv[9] * cy + Tv[10] * cz + Tv[11];

    const float* Kv = Kmat + v * 9;    // 3x3 row-major
    const float q0 = Kv[0] * pc0 + Kv[1] * pc1 + Kv[2] * pc2;
    const float q1 = Kv[3] * pc0 + Kv[4] * pc1 + Kv[5] * pc2;
    const float q2 = Kv[6] * pc0 + Kv[7] * pc1 + Kv[8] * pc2;

    const float z  = pc2;
    const float u  = q0 / q2;          // ref: u = p2d.x / p2d.z
    const float vv = q1 / z;           // ref: v = p2d.y / p_cam.z

    const float Himg = (float)img_sizes[v * 2 + 0];
    const float Wimg = (float)img_sizes[v * 2 + 1];
    const int u0 = (int)floorf(u  * (float)WF / Wimg);
    const int v0 = (int)floorf(vv * (float)HF / Himg);

    const bool valid = (z > 0.0f) && (u >= 0.0f) && (u < Wimg) &&
                       (vv >= 0.0f) && (vv < Himg) &&
                       (u0 < WF - 1) && (v0 < HF - 1);

    const int u0c = min(max(u0, 0), WF - 2);
    const int v0c = min(max(v0, 0), HF - 2);
    *coord_out = u0c | (v0c << 8);
    return valid ? 1 : 0;
}

__global__ void __launch_bounds__(NTHR, 1)
fused_kernel(const float* __restrict__ boxes,
             const float* __restrict__ feats,
             const float* __restrict__ Kmat,
             const float* __restrict__ Tmat,
             const int*   __restrict__ img_sizes,
             float*       __restrict__ out)
{
    __shared__ int   s_first;
    __shared__ float s_sinv;
    __shared__ float s_stored[C_FEAT];
    __shared__ float s_pdot[NPAIRW][2];
    __shared__ float s_pnrm[NPAIRW][2];
    __shared__ float s_loss[NPAIRW];
    __shared__ int   s_lval[NPAIRW];

    const int tid  = threadIdx.x;
    const int warp = tid >> 5;
    const int lane = tid & 31;

    if (warp == 22) {
        // ================= Scout warp =================
        // first = min(p | valid) by ballot chunk-scan.
        int first = 0, fcoord = 0, coord_p0 = 0;
        for (int c = 0; c < NCHUNK; c++) {
            int coord;
            const int valid = project_pair(c * 32 + lane, boxes, Kmat, Tmat,
                                           img_sizes, &coord);
            if (c == 0) coord_p0 = __shfl_sync(0xffffffffu, coord, 0);
            const unsigned m = __ballot_sync(0xffffffffu, valid);
            if (m) {
                const int lead = __ffs(m) - 1;
                first  = c * 32 + lead;
                fcoord = __shfl_sync(0xffffffffu, coord, lead);
                break;
            }
            if (c == NCHUNK - 1) { first = 0; fcoord = coord_p0; } // none valid
        }

        // Gather 'stored' with the pair-lane line-sharing trick.
        const int u0f   = fcoord & 0xFF;
        const int v0f   = (fcoord >> 8) & 0xFF;
        const int viewf = first % N_VIEWS;
        const int du    = lane & 1;
        const int chof  = lane >> 1;
        const float* base = feats + (size_t)viewf * C_FEAT * HW
                                  + (size_t)v0f * WF + u0f + du;
        float y0[16], y1[16];
        #pragma unroll
        for (int i = 0; i < 16; i++) {
            const float* pch = base + (size_t)(chof + i * 16) * HW;
            y0[i] = pch[0];
            y1[i] = pch[WF];
        }
        float sq = 0.0f;
        #pragma unroll
        for (int i = 0; i < 16; i++) {
            const float s2 = y0[i] + y1[i];
            const float sp = __shfl_xor_sync(0xffffffffu, s2, 1);
            const float fm = 0.25f * (s2 + sp);
            if (du == 0) s_stored[chof + i * 16] = fm;
            sq += fm * fm;                 // counted by both du-lanes
        }
        #pragma unroll
        for (int o = 16; o > 0; o >>= 1)
            sq += __shfl_xor_sync(0xffffffffu, sq, o);
        if (lane == 0) {
            s_first = first;
            s_sinv  = 1.0f / fmaxf(sqrtf(0.5f * sq), EPS);
        }
        __syncthreads();   // (1) publish stored/sinv/first
        __syncthreads();   // (2) match pair warps' loss barrier
    } else if (warp < 22) {
        // ============== Pair-half warps (0..21) ==============
        // warp = 2*ph + half : half handles channels [half*128, half*128+128)
        const int ph    = warp >> 1;
        const int half  = warp & 1;
        const int p_own = blockIdx.x + NBLK * ph;
        float y0[8], y1[8];
        int own_coord = 0, own_valid = 0;
        if (p_own < P_TOT)
            own_valid = project_pair(p_own, boxes, Kmat, Tmat, img_sizes,
                                     &own_coord);
        const int du   = lane & 1;
        const int chof = (lane >> 1) + half * 128;   // 0..15 | 128..143
        if (own_valid) {
            const int u0   = own_coord & 0xFF;
            const int v0   = (own_coord >> 8) & 0xFF;
            const int view = p_own % N_VIEWS;
            const float* base = feats + (size_t)view * C_FEAT * HW
                                      + (size_t)v0 * WF + u0 + du;
            #pragma unroll
            for (int i = 0; i < 8; i++) {
                const float* pch = base + (size_t)(chof + i * 16) * HW;
                y0[i] = pch[0];      // row v0
                y1[i] = pch[WF];     // row v0+1
            }
        } else {
            #pragma unroll
            for (int i = 0; i < 8; i++) { y0[i] = 0.0f; y1[i] = 0.0f; }
        }
        // Pre-reduce fm + self-norm partial before the barrier.
        float fm[8];
        float nrm = 0.0f;
        #pragma unroll
        for (int i = 0; i < 8; i++) {
            const float s2 = y0[i] + y1[i];
            const float sp = __shfl_xor_sync(0xffffffffu, s2, 1);
            fm[i] = 0.25f * (s2 + sp);
            nrm += fm[i] * fm[i];
        }

        __syncthreads();   // (1) stored/sinv/first ready

        float dot = 0.0f;
        #pragma unroll
        for (int i = 0; i < 8; i++)
            dot += fm[i] * s_stored[chof + i * 16];
        #pragma unroll
        for (int o = 16; o > 0; o >>= 1) {
            dot += __shfl_xor_sync(0xffffffffu, dot, o);
            nrm += __shfl_xor_sync(0xffffffffu, nrm, o);
        }
        if (lane == 0) {
            s_pdot[ph][half] = dot;   // each channel counted by both du lanes
            s_pnrm[ph][half] = nrm;
        }
        __syncthreads();   // (2) halves visible

        if (half == 0 && lane == 0) {
            float loss = 0.0f;
            int   cnt  = 0;
            if (own_valid && p_own != s_first) {
                const float d = 0.5f * (s_pdot[ph][0] + s_pdot[ph][1]);
                const float n = 0.5f * (s_pnrm[ph][0] + s_pnrm[ph][1]);
                const float inv_i = 1.0f / fmaxf(sqrtf(n), EPS);
                loss = 1.0f - d * inv_i * s_sinv;
                cnt  = 1;
            }
            s_loss[ph] = loss;
            s_lval[ph] = cnt;
        }
    } else {
        // warp 23: idle, just match barriers
        __syncthreads();   // (1)
        __syncthreads();   // (2)
    }

    __syncthreads();       // (3) s_loss/s_lval visible to tid 0

    // ---- Deterministic block sum -> fixed-point global atomics ----
    if (tid == 0) {
        float bsum = 0.0f;
        int   bcnt = 0;
        #pragma unroll
        for (int k = 0; k < NPAIRW; k++) { bsum += s_loss[k]; bcnt += s_lval[k]; }
        const long long q = llrint((double)bsum * FSCALE);
        atomicAdd(&g_sum, (unsigned long long)q);
        atomicAdd(&g_cnt, bcnt);
        __threadfence();
        const int done = atomicAdd(&g_done, 1);
        if (done == NBLK - 1) {
            const long long tot = (long long)atomicAdd(&g_sum, 0ULL);
            const int n = atomicAdd(&g_cnt, 0);
            out[0] = (n > 0) ? (float)(((double)tot / FSCALE) / (double)n) : 0.0f;
            // reset for next replay (kernel boundary orders this vs next launch)
            g_sum = 0ULL; g_cnt = 0; g_done = 0;
        }
    }
}

extern "C" void kernel_launch(void* const* d_in, const int* in_sizes, int n_in,
                              void* d_out, int out_size)
{
    const float* boxes     = (const float*)d_in[0];  // (256, 7)
    const float* feats     = (const float*)d_in[1];  // (6, 256, 116, 200)
    const float* Kmat      = (const float*)d_in[2];  // (6, 3, 3)
    const float* Tmat      = (const float*)d_in[3];  // (6, 4, 4)
    const int*   img_sizes = (const int*)d_in[4];    // (6, 2)
    float* out = (float*)d_out;

    fused_kernel<<<NBLK, NTHR>>>(boxes, feats, Kmat, Tmat, img_sizes, out);
}